// round 11
// baseline (speedup 1.0000x reference)
#include <cuda_runtime.h>

// BioSelfAttention — fused, closed-form LIF, minimal-MIO version.
//
// Pipeline: QK dots -> LIF -> WTA(T=128) -> r*V -> LIF -> WTA(T*D=8192).
// One block per (b,h) slice (B*H = 32), 512 threads.
//
// WTA step: x_i <- clip(3*x_i - 0.9*S, 0, 1), S = sum x (W = inh + (exc-inh)I).
// Exact fixed points => bitwise-stationary early exit is numerically exact.
// LIF closed form: spikes periodic, t1 = ceil(ln(1-1/J)/ln 0.95),
// count over 100 steps = floor(100/t1).

#define NBH 32

__device__ __forceinline__ float lif_rate_cf(float J) {
    if (J <= 1.0f) return 0.0f;                      // v_inf = J < 1: no spike
    float ratio = logf(1.0f - 1.0f / J) * (-19.4957257f);   // 1/ln(0.95)
    if (!(ratio <= 100.0f)) return 0.0f;             // no spike in 100 steps
    int t1 = (int)ceilf(ratio);
    if (t1 < 1) t1 = 1;
    return (float)(100 / t1) * 0.01f;                // floor(100/t1)/100
}

__global__ void __launch_bounds__(512)
k_bio_fused(const float* __restrict__ Q, const float* __restrict__ K,
            const float* __restrict__ V, float* __restrict__ out) {
    const int tid  = threadIdx.x;
    const int wid  = tid >> 5;     // 0..15
    const int lane = tid & 31;

    __shared__ float sP[512];      // stage-A partial dots
    __shared__ float sR[128];      // token rates
    __shared__ float sw[16];       // stage-E per-warp sums

    const size_t base = (size_t)blockIdx.x * 8192;
    const float* Qb = Q + base;
    const float* Kb = K + base;
    const float* Vb = V + base;
    float*       Ob = out + base;

    // ---- Stage A: QK partial dots, SHFL-free. 4 threads per token, each
    //      owns 16 consecutive columns (4 float4 of Q + 4 of K, coalesced). ----
    {
        const int tok = tid >> 2;
        const int seg = (tid & 3) << 2;              // float4 index 0,4,8,12
        const float4* qr = reinterpret_cast<const float4*>(Qb + tok * 64);
        const float4* kr = reinterpret_cast<const float4*>(Kb + tok * 64);
        float acc0 = 0.0f, acc1 = 0.0f;
        #pragma unroll
        for (int i = 0; i < 4; i += 2) {
            float4 q0 = qr[seg + i],     k0 = kr[seg + i];
            float4 q1 = qr[seg + i + 1], k1 = kr[seg + i + 1];
            acc0 += q0.x * k0.x + q0.y * k0.y + q0.z * k0.z + q0.w * k0.w;
            acc1 += q1.x * k1.x + q1.y * k1.y + q1.z * k1.z + q1.w * k1.w;
        }
        sP[tid] = acc0 + acc1;
    }
    __syncthreads();

    // ---- Stage B: 128 threads finish the dots (1 LDS.128) + closed-form LIF. ----
    if (tid < 128) {
        float4 p4 = reinterpret_cast<const float4*>(sP)[tid];
        sR[tid] = lif_rate_cf((p4.x + p4.y) + (p4.z + p4.w));
    }
    __syncthreads();

    // ---- Stage C: WTA over T=128 in WARP 0 ONLY (10 SHFLs total for the
    //      executed 2 iterations, instead of 32x redundant). ----
    if (wid == 0) {
        float y[4];
        #pragma unroll
        for (int j = 0; j < 4; ++j) y[j] = sR[lane + 32 * j];
        for (int it = 0; it < 20; ++it) {
            float l = (y[0] + y[1]) + (y[2] + y[3]);
            #pragma unroll
            for (int off = 16; off; off >>= 1)
                l += __shfl_xor_sync(0xffffffffu, l, off);
            bool same = true;
            #pragma unroll
            for (int j = 0; j < 4; ++j) {
                float ny = fminf(fmaxf(fmaf(3.0f, y[j], -0.9f * l), 0.0f), 1.0f);
                same &= (ny == y[j]);
                y[j] = ny;
            }
            if (__all_sync(0xffffffffu, same)) break;   // exact fixed point
        }
        #pragma unroll
        for (int j = 0; j < 4; ++j) sR[lane + 32 * j] = y[j];
    }
    __syncthreads();

    // ---- Stage D: J_v = rate * V, closed-form LIF. Each thread owns 16
    //      consecutive output elements (token = tid/4). Rate read via LDS
    //      broadcast; zero-rate tokens skip the V loads entirely. ----
    float z[16];
    {
        const float r = sR[tid >> 2];
        if (r != 0.0f) {
            const float4* vr = reinterpret_cast<const float4*>(Vb) + (tid << 2);
            #pragma unroll
            for (int i = 0; i < 4; ++i) {
                float4 v4 = vr[i];
                z[i * 4 + 0] = lif_rate_cf(r * v4.x);
                z[i * 4 + 1] = lif_rate_cf(r * v4.y);
                z[i * 4 + 2] = lif_rate_cf(r * v4.z);
                z[i * 4 + 3] = lif_rate_cf(r * v4.w);
            }
        } else {
            #pragma unroll
            for (int i = 0; i < 16; ++i) z[i] = 0.0f;
        }
    }

    // ---- Stage E: WTA over T*D=8192, 16 values/thread, 16 warps.
    //      Block sum: per-warp butterfly -> sw -> 4-level butterfly over 16.
    //      S is bitwise-identical in every warp => uniform early exits. ----
    for (int it = 0; it < 20; ++it) {
        float l = 0.0f;
        #pragma unroll
        for (int i = 0; i < 16; ++i) l += z[i];
        #pragma unroll
        for (int off = 16; off; off >>= 1)
            l += __shfl_xor_sync(0xffffffffu, l, off);
        if (lane == 0) sw[wid] = l;
        __syncthreads();
        float S = sw[lane & 15];
        #pragma unroll
        for (int off = 8; off; off >>= 1)
            S += __shfl_xor_sync(0xffffffffu, S, off);
        if (S == 0.0f) break;            // all-zero: exact fixed point (uniform)
        int same = 1;
        #pragma unroll
        for (int i = 0; i < 16; ++i) {
            float nz = fminf(fmaxf(fmaf(3.0f, z[i], -0.9f * S), 0.0f), 1.0f);
            same &= (nz == z[i]);
            z[i] = nz;
        }
        if (__syncthreads_and(same)) break;   // barrier + block-uniform vote
    }

    // ---- Store: 4 STG.128 per thread, fully coalesced. ----
    {
        float4* orow = reinterpret_cast<float4*>(Ob) + (tid << 2);
        #pragma unroll
        for (int i = 0; i < 4; ++i)
            orow[i] = make_float4(z[i * 4], z[i * 4 + 1], z[i * 4 + 2], z[i * 4 + 3]);
    }
}

extern "C" void kernel_launch(void* const* d_in, const int* in_sizes, int n_in,
                              void* d_out, int out_size) {
    const float* Q = (const float*)d_in[0];
    const float* K = (const float*)d_in[1];
    const float* V = (const float*)d_in[2];
    k_bio_fused<<<NBH, 512>>>(Q, K, V, (float*)d_out);
}